// round 11
// baseline (speedup 1.0000x reference)
#include <cuda_runtime.h>

// FiringRateModel: T-step scalar-feedback linear recurrence, B independent chains.
//
// Same algebra as R9 (proven rel_err 8.65e-7):
//   V(t)  = D∘V(t-1) + c_t*D2A + f(t-1)*D2B          (wide, 3 f2-ops/pair)
//   z(t)  = S2(t-2) + c_t*SA + c_{t-1}*SDA + f(t-1)*SB + f(t-2)*SDB - gb
//   f(t)  = max(0, 200 - 400/(1 + 2^(K*poly(z))))
//   S2 reduction software-pipelined: tree at end of body t, shfl pair in body t+1.
//
// KEY CHANGE vs R9: the phi chain (12 dependent instrs, ~65 cyc) is manually
// INTERLEAVED with the independent wide/tree packed ops so in-order issue
// never blocks more than a few cycles: each phi link is followed in program
// order by ready-to-issue f2 ops. R9 evidence: issue 51% with a contiguous
// phi block = both warps stall in phi simultaneously; floor is ~184 cyc/step
// (46 fma-instrs/warp x 2 warps x rt2), measured 274 -> ~90 cyc of issue holes.
//
// R=4 lanes/chain, TPB=256, grid=128 -> 2 warps/SMSP (best measured shape).

#define TPB 256

typedef unsigned long long u64p;

__device__ __forceinline__ u64p pk2(float lo, float hi) {
    u64p r;
    asm("mov.b64 %0, {%1,%2};" : "=l"(r) : "r"(__float_as_uint(lo)), "r"(__float_as_uint(hi)));
    return r;
}
__device__ __forceinline__ void upk2(u64p v, float &lo, float &hi) {
    unsigned int l, h;
    asm("mov.b64 {%0,%1}, %2;" : "=r"(l), "=r"(h) : "l"(v));
    lo = __uint_as_float(l); hi = __uint_as_float(h);
}
__device__ __forceinline__ u64p f2fma(u64p a, u64p b, u64p c) {
    u64p d;
    asm("fma.rn.f32x2 %0, %1, %2, %3;" : "=l"(d) : "l"(a), "l"(b), "l"(c));
    return d;
}
__device__ __forceinline__ u64p f2mul(u64p a, u64p b) {
    u64p d;
    asm("mul.rn.f32x2 %0, %1, %2;" : "=l"(d) : "l"(a), "l"(b));
    return d;
}
__device__ __forceinline__ u64p f2add(u64p a, u64p b) {
    u64p d;
    asm("add.rn.f32x2 %0, %1, %2;" : "=l"(d) : "l"(a), "l"(b));
    return d;
}
__device__ __forceinline__ float ex2a(float x) {
    float r; asm("ex2.approx.f32 %0, %1;" : "=f"(r) : "f"(x)); return r;
}
__device__ __forceinline__ float rcpa(float x) {
    float r; asm("rcp.approx.f32 %0, %1;" : "=f"(r) : "f"(x)); return r;
}

__global__ void __launch_bounds__(TPB, 1)
fr_kernel(const float* __restrict__ cur,   // [T, B]
          const float* __restrict__ fs0,   // [B]
          const float* __restrict__ av,    // [N]
          const float* __restrict__ bv,    // [N]
          const float* __restrict__ wv,    // [N]
          const float* __restrict__ dsv,   // [N]
          const float* __restrict__ pc,    // [6]
          const float* __restrict__ gbp,   // [1]
          float* __restrict__ out,         // [T, B]
          int T, int B)
{
    int tid = blockIdx.x * TPB + threadIdx.x;
    int chain = tid >> 2;        // one chain per 4 lanes
    int r = tid & 3;
    if (chain >= B) return;
    int nb = r * 16;             // 16 neurons = 8 packed pairs per lane

    // Polynomial coefficients, squared per reference, K = 2*log2(e) folded in.
    const float K = 2.885390081777927f;
    float C0 = K * pc[0] * pc[0], C1 = K * pc[1] * pc[1], C2 = K * pc[2] * pc[2];
    float C3 = K * pc[3] * pc[3], C4 = K * pc[4] * pc[4], C5 = K * pc[5] * pc[5];
    float gb = gbp[0] * 0.01f;

    // Per-lane constants. A' = a*w/100, B' = 10*b*w, D = 1-ds.
    // D2A = D^2∘A', D2B = D^2∘B'.  (state V = D^2∘u -> plain-add tree)
    u64p D[8], D2A[8], D2B[8], V[8];
    float sap = 0.f, sbp = 0.f, sdap = 0.f, sdbp = 0.f;
    #pragma unroll
    for (int j = 0; j < 8; j++) {
        int n0 = nb + 2 * j;
        float w0 = wv[n0],            w1 = wv[n0 + 1];
        float d0 = 1.f - dsv[n0],     d1 = 1.f - dsv[n0 + 1];
        float a0 = av[n0] * w0 * 0.01f, a1 = av[n0 + 1] * w1 * 0.01f;
        float b0 = 10.f * bv[n0] * w0,  b1 = 10.f * bv[n0 + 1] * w1;
        D[j]   = pk2(d0, d1);
        D2A[j] = pk2(d0 * d0 * a0, d1 * d1 * a1);
        D2B[j] = pk2(d0 * d0 * b0, d1 * d1 * b1);
        V[j]   = 0ull;
        sap  += a0 + a1;
        sbp  += b0 + b1;
        sdap += d0 * a0 + d1 * a1;
        sdbp += d0 * b0 + d1 * b1;
    }
    #pragma unroll
    for (int m = 1; m <= 2; m <<= 1) {
        sap  += __shfl_xor_sync(0xffffffffu, sap,  m);
        sbp  += __shfl_xor_sync(0xffffffffu, sbp,  m);
        sdap += __shfl_xor_sync(0xffffffffu, sdap, m);
        sdbp += __shfl_xor_sync(0xffffffffu, sdbp, m);
    }
    const float SA = sap, SB = sbp, SDA = sdap, SDB = sdbp;

    float f1 = fs0[chain];       // f(t-1)
    float fx2 = 0.f;             // f(t-2)
    float Wprev = 0.f;           // S2(t-2) at top of body t
    float pend = 0.f;            // in-lane tree sum of V(t-1), awaiting shfls

    const float* cp = cur + chain;         // initial ring fill
    const float* lp = cp + (size_t)8 * B;  // prefetch pointer -> c_{t+8}
    float* op = out + chain;

    // Prefetch rings: cb[i] = c_i (raw), cs[i] = c_i*SA + c_{i-1}*SDA - gb.
    float cb[8], cs[8];
    {
        float cl = 0.f;          // c_{-1} = 0
        #pragma unroll
        for (int i = 0; i < 8; i++) {
            cb[i] = cp[(size_t)i * B];
            cs[i] = fmaf(cb[i], SA, fmaf(cl, SDA, -gb));
            cl = cb[i];
        }
    }
    float clast = cb[7];

    // One step, with the serial phi chain interleaved among independent
    // packed ops so in-order issue never starves. kk = step index for
    // indexed output (op advances 8*B per unrolled group).
    #define FR_STEP(craw, cpre, kk)                                            \
    {                                                                          \
        u64p c2  = pk2((craw), (craw));                                        \
        u64p f2r = pk2(f1, f1);                                                \
        /* phi link 1 (operands: lag-2 sum, f(t-2), f(t-1) -- all ready) */    \
        float base = fmaf(fx2, SDB, Wprev + (cpre));                           \
        float x = fmaf(f1, SB, base);                                          \
        /* wide 0-1 */                                                         \
        V[0] = f2fma(D[0], V[0], f2fma(D2B[0], f2r, f2mul(D2A[0], c2)));       \
        V[1] = f2fma(D[1], V[1], f2fma(D2B[1], f2r, f2mul(D2A[1], c2)));       \
        /* phi link 2 */                                                       \
        float x2  = x * x;                                                     \
        float e01 = fmaf(C1, x, C0);                                           \
        float e23 = fmaf(C3, x, C2);                                           \
        float e45 = fmaf(C5, x, C4);                                           \
        /* wide 2-3 */                                                         \
        V[2] = f2fma(D[2], V[2], f2fma(D2B[2], f2r, f2mul(D2A[2], c2)));       \
        V[3] = f2fma(D[3], V[3], f2fma(D2B[3], f2r, f2mul(D2A[3], c2)));       \
        /* phi link 3 */                                                       \
        float x4 = x2 * x2;                                                    \
        float q  = fmaf(x2, e23, e01);                                         \
        /* wide 4-5 */                                                         \
        V[4] = f2fma(D[4], V[4], f2fma(D2B[4], f2r, f2mul(D2A[4], c2)));       \
        V[5] = f2fma(D[5], V[5], f2fma(D2B[5], f2r, f2mul(D2A[5], c2)));       \
        /* phi link 4 */                                                       \
        q = fmaf(x4, e45, q);                          /* q = K*poly(x) */     \
        /* wide 6-7 */                                                         \
        V[6] = f2fma(D[6], V[6], f2fma(D2B[6], f2r, f2mul(D2A[6], c2)));       \
        V[7] = f2fma(D[7], V[7], f2fma(D2B[7], f2r, f2mul(D2A[7], c2)));       \
        /* phi link 5: MUFU (16 cyc) -- cover with shfls on last step's sum */ \
        float e = ex2a(q);                                                     \
        float sp = pend;                                                       \
        sp += __shfl_xor_sync(0xffffffffu, sp, 1);                             \
        sp += __shfl_xor_sync(0xffffffffu, sp, 2);                             \
        /* tree half over fresh V */                                           \
        u64p g0 = f2add(f2add(V[0], V[1]), f2add(V[2], V[3]));                 \
        /* phi link 6: rcp MUFU -- cover with rest of tree */                  \
        float epn = e + 1.f;                                                   \
        float rr = rcpa(epn);                                                  \
        u64p g1 = f2add(f2add(V[4], V[5]), f2add(V[6], V[7]));                 \
        u64p gt = f2add(g0, g1);                                               \
        /* phi link 7 */                                                       \
        float fn = fmaf(rr, -400.f, 200.f);                                    \
        fn = fmaxf(fn, 0.f);                                                   \
        float lo, hi; upk2(gt, lo, hi);                                        \
        pend = lo + hi;                                                        \
        Wprev = sp;                                                            \
        if (r == 0) op[(size_t)(kk) * B] = fn;                                 \
        fx2 = f1;                                                              \
        f1 = fn;                                                               \
    }

    // Main loop: steps [0, T-8), refill rings at distance 8
    for (int t = 0; t < T - 8; t += 8) {
        #pragma unroll
        for (int k = 0; k < 8; k++) {
            float craw = cb[k];
            float cpre = cs[k];
            float cnew = lp[(size_t)k * B];
            cb[k] = cnew;
            cs[k] = fmaf(cnew, SA, fmaf(clast, SDA, -gb));
            clast = cnew;
            FR_STEP(craw, cpre, k)
        }
        lp += (size_t)8 * B;
        op += (size_t)8 * B;
    }
    // Epilogue: last 8 steps, no loads
    #pragma unroll
    for (int k = 0; k < 8; k++) {
        FR_STEP(cb[k], cs[k], k)
    }
    #undef FR_STEP
}

extern "C" void kernel_launch(void* const* d_in, const int* in_sizes, int n_in,
                              void* d_out, int out_size) {
    const float* cur = (const float*)d_in[0];   // currents [T*B]
    const float* fs0 = (const float*)d_in[1];   // [B]
    const float* av  = (const float*)d_in[2];   // [N]
    const float* bv  = (const float*)d_in[3];   // [N]
    const float* wv  = (const float*)d_in[4];   // [N,1]
    const float* dsv = (const float*)d_in[5];   // [N]
    const float* pc  = (const float*)d_in[6];   // [DEG+1]
    const float* gbp = (const float*)d_in[7];   // scalar

    int B = in_sizes[1];
    int T = in_sizes[0] / B;

    int threads = B * 4;                        // 4 lanes per chain
    int blocks = (threads + TPB - 1) / TPB;
    fr_kernel<<<blocks, TPB>>>(cur, fs0, av, bv, wv, dsv, pc, gbp,
                               (float*)d_out, T, B);
}

// round 12
// speedup vs baseline: 1.0150x; 1.0150x over previous
#include <cuda_runtime.h>

// FiringRateModel: T-step scalar-feedback linear recurrence, B independent chains.
//
// Algebra (proven rel_err 8.65e-7):
//   V(t)  = D∘V(t-1) + c_t*D2A + f(t-1)*D2B          (wide, 3 f2-ops/pair)
//   z(t)  = S2(t-2) + c_t*SA + c_{t-1}*SDA + f(t-1)*SB + f(t-2)*SDB - gb
//   f(t)  = max(0, 200 - 400/(1 + 2^(K*poly(z))))
//   S2 reduction software-pipelined: tree at end of body t, shfl pair in body t+1.
//
// KEY CHANGE vs R9/R11: the ring refill previously computed
// cs[k]=fma(cnew,...) IMMEDIATELY from the just-issued LDG -> every warp
// hard-stalled ~250 cyc/step on the load scoreboard. That stall explains the
// ~300 cyc/step invariance across all shapes (R=2/4/8, 1/2/4 warps) and the
// pinned 51% issue. Now the refill is a pure register write (cb[k] = LDG),
// first consumed 8 steps (~1600 cyc) later; the c-terms are computed inline
// from ring values that are already 8 steps old.
//
// R=4 lanes/chain, TPB=256, grid=128 -> 2 warps/SMSP.

#define TPB 256

typedef unsigned long long u64p;

__device__ __forceinline__ u64p pk2(float lo, float hi) {
    u64p r;
    asm("mov.b64 %0, {%1,%2};" : "=l"(r) : "r"(__float_as_uint(lo)), "r"(__float_as_uint(hi)));
    return r;
}
__device__ __forceinline__ void upk2(u64p v, float &lo, float &hi) {
    unsigned int l, h;
    asm("mov.b64 {%0,%1}, %2;" : "=r"(l), "=r"(h) : "l"(v));
    lo = __uint_as_float(l); hi = __uint_as_float(h);
}
__device__ __forceinline__ u64p f2fma(u64p a, u64p b, u64p c) {
    u64p d;
    asm("fma.rn.f32x2 %0, %1, %2, %3;" : "=l"(d) : "l"(a), "l"(b), "l"(c));
    return d;
}
__device__ __forceinline__ u64p f2mul(u64p a, u64p b) {
    u64p d;
    asm("mul.rn.f32x2 %0, %1, %2;" : "=l"(d) : "l"(a), "l"(b));
    return d;
}
__device__ __forceinline__ u64p f2add(u64p a, u64p b) {
    u64p d;
    asm("add.rn.f32x2 %0, %1, %2;" : "=l"(d) : "l"(a), "l"(b));
    return d;
}
__device__ __forceinline__ float ex2a(float x) {
    float r; asm("ex2.approx.f32 %0, %1;" : "=f"(r) : "f"(x)); return r;
}
__device__ __forceinline__ float rcpa(float x) {
    float r; asm("rcp.approx.f32 %0, %1;" : "=f"(r) : "f"(x)); return r;
}

__global__ void __launch_bounds__(TPB, 1)
fr_kernel(const float* __restrict__ cur,   // [T, B]
          const float* __restrict__ fs0,   // [B]
          const float* __restrict__ av,    // [N]
          const float* __restrict__ bv,    // [N]
          const float* __restrict__ wv,    // [N]
          const float* __restrict__ dsv,   // [N]
          const float* __restrict__ pc,    // [6]
          const float* __restrict__ gbp,   // [1]
          float* __restrict__ out,         // [T, B]
          int T, int B)
{
    int tid = blockIdx.x * TPB + threadIdx.x;
    int chain = tid >> 2;        // one chain per 4 lanes
    int r = tid & 3;
    if (chain >= B) return;
    int nb = r * 16;             // 16 neurons = 8 packed pairs per lane

    // Polynomial coefficients, squared per reference, K = 2*log2(e) folded in.
    const float K = 2.885390081777927f;
    float C0 = K * pc[0] * pc[0], C1 = K * pc[1] * pc[1], C2 = K * pc[2] * pc[2];
    float C3 = K * pc[3] * pc[3], C4 = K * pc[4] * pc[4], C5 = K * pc[5] * pc[5];
    float gb = gbp[0] * 0.01f;

    // Per-lane constants. A' = a*w/100, B' = 10*b*w, D = 1-ds.
    // D2A = D^2∘A', D2B = D^2∘B'.  (state V = D^2∘u -> plain-add tree)
    u64p D[8], D2A[8], D2B[8], V[8];
    float sap = 0.f, sbp = 0.f, sdap = 0.f, sdbp = 0.f;
    #pragma unroll
    for (int j = 0; j < 8; j++) {
        int n0 = nb + 2 * j;
        float w0 = wv[n0],            w1 = wv[n0 + 1];
        float d0 = 1.f - dsv[n0],     d1 = 1.f - dsv[n0 + 1];
        float a0 = av[n0] * w0 * 0.01f, a1 = av[n0 + 1] * w1 * 0.01f;
        float b0 = 10.f * bv[n0] * w0,  b1 = 10.f * bv[n0 + 1] * w1;
        D[j]   = pk2(d0, d1);
        D2A[j] = pk2(d0 * d0 * a0, d1 * d1 * a1);
        D2B[j] = pk2(d0 * d0 * b0, d1 * d1 * b1);
        V[j]   = 0ull;
        sap  += a0 + a1;
        sbp  += b0 + b1;
        sdap += d0 * a0 + d1 * a1;
        sdbp += d0 * b0 + d1 * b1;
    }
    #pragma unroll
    for (int m = 1; m <= 2; m <<= 1) {
        sap  += __shfl_xor_sync(0xffffffffu, sap,  m);
        sbp  += __shfl_xor_sync(0xffffffffu, sbp,  m);
        sdap += __shfl_xor_sync(0xffffffffu, sdap, m);
        sdbp += __shfl_xor_sync(0xffffffffu, sdbp, m);
    }
    const float SA = sap, SB = sbp, SDA = sdap, SDB = sdbp;

    float f1 = fs0[chain];       // f(t-1)
    float fx2 = 0.f;             // f(t-2)
    float Wprev = 0.f;           // S2(t-2) at top of body t
    float pend = 0.f;            // in-lane tree sum of V(t-1), awaiting shfls
    float cprev = 0.f;           // c_{t-1} (raw, always >=8 steps post-load)

    const float* cp = cur + chain;         // initial ring fill
    const float* lp = cp + (size_t)8 * B;  // prefetch pointer -> c_{t+8}
    float* op = out + chain;

    // Prefetch ring: cb[i] = c_i (raw only; derived terms computed at USE
    // time, 8 steps after the load, so no consumer chases the LDG).
    float cb[8];
    #pragma unroll
    for (int i = 0; i < 8; i++) cb[i] = cp[(size_t)i * B];

    // One step. craw = c_t (loaded 8 steps ago). All c-math inline on old data.
    #define FR_STEP(craw, kk)                                                  \
    {                                                                          \
        /* c-terms: operands 8 steps old -> issue without stall */             \
        float cpre = fmaf((craw), SA, fmaf(cprev, SDA, -gb));                  \
        u64p c2  = pk2((craw), (craw));                                        \
        u64p f2r = pk2(f1, f1);                                                \
        /* phi link 1 */                                                       \
        float base = fmaf(fx2, SDB, Wprev + cpre);                             \
        float x = fmaf(f1, SB, base);                                          \
        /* wide 0-1 */                                                         \
        V[0] = f2fma(D[0], V[0], f2fma(D2B[0], f2r, f2mul(D2A[0], c2)));       \
        V[1] = f2fma(D[1], V[1], f2fma(D2B[1], f2r, f2mul(D2A[1], c2)));       \
        /* phi link 2 */                                                       \
        float x2  = x * x;                                                     \
        float e01 = fmaf(C1, x, C0);                                           \
        float e23 = fmaf(C3, x, C2);                                           \
        float e45 = fmaf(C5, x, C4);                                           \
        /* wide 2-3 */                                                         \
        V[2] = f2fma(D[2], V[2], f2fma(D2B[2], f2r, f2mul(D2A[2], c2)));       \
        V[3] = f2fma(D[3], V[3], f2fma(D2B[3], f2r, f2mul(D2A[3], c2)));       \
        /* phi link 3 */                                                       \
        float x4 = x2 * x2;                                                    \
        float q  = fmaf(x2, e23, e01);                                         \
        /* wide 4-5 */                                                         \
        V[4] = f2fma(D[4], V[4], f2fma(D2B[4], f2r, f2mul(D2A[4], c2)));       \
        V[5] = f2fma(D[5], V[5], f2fma(D2B[5], f2r, f2mul(D2A[5], c2)));       \
        /* phi link 4 */                                                       \
        q = fmaf(x4, e45, q);                          /* q = K*poly(x) */     \
        /* wide 6-7 */                                                         \
        V[6] = f2fma(D[6], V[6], f2fma(D2B[6], f2r, f2mul(D2A[6], c2)));       \
        V[7] = f2fma(D[7], V[7], f2fma(D2B[7], f2r, f2mul(D2A[7], c2)));       \
        /* phi link 5: MUFU -- covered by shfls on last step's tree sum */     \
        float e = ex2a(q);                                                     \
        float sp = pend;                                                       \
        sp += __shfl_xor_sync(0xffffffffu, sp, 1);                             \
        sp += __shfl_xor_sync(0xffffffffu, sp, 2);                             \
        /* tree half over fresh V */                                           \
        u64p g0 = f2add(f2add(V[0], V[1]), f2add(V[2], V[3]));                 \
        /* phi link 6: rcp MUFU -- covered by rest of tree */                  \
        float epn = e + 1.f;                                                   \
        float rr = rcpa(epn);                                                  \
        u64p g1 = f2add(f2add(V[4], V[5]), f2add(V[6], V[7]));                 \
        u64p gt = f2add(g0, g1);                                               \
        /* phi link 7 */                                                       \
        float fn = fmaf(rr, -400.f, 200.f);                                    \
        fn = fmaxf(fn, 0.f);                                                   \
        float lo, hi; upk2(gt, lo, hi);                                        \
        pend = lo + hi;                                                        \
        Wprev = sp;                                                            \
        if (r == 0) op[(size_t)(kk) * B] = fn;                                 \
        cprev = (craw);                                                        \
        fx2 = f1;                                                              \
        f1 = fn;                                                               \
    }

    // Main loop: steps [0, T-8). Refill is a PURE register write from LDG;
    // the loaded value is untouched for 8 steps (~1600 cyc of slack).
    for (int t = 0; t < T - 8; t += 8) {
        #pragma unroll
        for (int k = 0; k < 8; k++) {
            float craw = cb[k];
            cb[k] = lp[(size_t)k * B];
            FR_STEP(craw, k)
        }
        lp += (size_t)8 * B;
        op += (size_t)8 * B;
    }
    // Epilogue: last 8 steps, no loads
    #pragma unroll
    for (int k = 0; k < 8; k++) {
        FR_STEP(cb[k], k)
    }
    #undef FR_STEP
}

extern "C" void kernel_launch(void* const* d_in, const int* in_sizes, int n_in,
                              void* d_out, int out_size) {
    const float* cur = (const float*)d_in[0];   // currents [T*B]
    const float* fs0 = (const float*)d_in[1];   // [B]
    const float* av  = (const float*)d_in[2];   // [N]
    const float* bv  = (const float*)d_in[3];   // [N]
    const float* wv  = (const float*)d_in[4];   // [N,1]
    const float* dsv = (const float*)d_in[5];   // [N]
    const float* pc  = (const float*)d_in[6];   // [DEG+1]
    const float* gbp = (const float*)d_in[7];   // scalar

    int B = in_sizes[1];
    int T = in_sizes[0] / B;

    int threads = B * 4;                        // 4 lanes per chain
    int blocks = (threads + TPB - 1) / TPB;
    fr_kernel<<<blocks, TPB>>>(cur, fs0, av, bv, wv, dsv, pc, gbp,
                               (float*)d_out, T, B);
}